// round 15
// baseline (speedup 1.0000x reference)
#include <cuda_runtime.h>
#include <cstdint>

// neigh_Conv: out[n,c,h,w] = b[c] + sum_{k<8} W[c,k] * x[n,c+k,h,w]
// x: (16, 200, 128, 128) f32 -> out: (16, 193, 128, 128) f32
//
// R15: TMA 1D bulk staging. The cp.async (LDGSTS) design plateaued at 75%
// DRAM (depth curve 6->70,8->77,16->71; occupancy levers all failed) --
// the per-thread LSU path is the cap. Replace 256x16B LDGSTS per plane
// with ONE cp.async.bulk of 4KB per CTA per plane (each CTA owns 256
// contiguous float4 positions), completion via mbarrier expect_tx.
// Compute identical: diagonal zero-padded weights, 8-slot acc ring, STG.128.

#define HW4    4096   // 128*128/4 float4 per plane
#define CIN    200
#define OUTC   193
#define NCHUNK 8
#define CHG    25     // output channels per chunk (last: 18)
#define DEPTH  8
#define BLK    256
#define STAGEB (BLK * 16)   // 4096 bytes per stage

__global__ __launch_bounds__(BLK)
void neigh_conv_kernel(const float* __restrict__ x,
                       const float* __restrict__ Wg,   // (193, 8) row-major
                       const float* __restrict__ b,
                       float4* __restrict__ out) {
    __shared__ float4 stg[DEPTH * BLK];                 // 32 KB stages
    __shared__ float4 sDW[32 * 2];                      // dW[c], c=0..31
    __shared__ float  sB[32];
    __shared__ __align__(8) unsigned long long mbar[2 * DEPTH]; // full[8], empty[8]

    const int t     = threadIdx.x;
    const int cbase = blockIdx.y * CHG;
    const int nout  = min(CHG, OUTC - cbase);   // 25 or 18
    const int nin   = nout + 7;                 // 32 or 25

    // Diagonal weights: dW[c][k] = W[c-k][k] or 0.
    float* sDWf = (float*)sDW;
    if (t < BLK) {
        const int c = t >> 3, k = t & 7;        // t covers 32*8 = 256
        const int oc = c - k;
        sDWf[t] = ((unsigned)oc < (unsigned)nout) ? Wg[(cbase + oc) * 8 + k] : 0.0f;
    }
    if (t < 32) sB[t] = (t < nout) ? b[cbase + t] : 0.0f;

    const unsigned mb = (unsigned)__cvta_generic_to_shared(mbar);
    #define FULLB(s)  (mb + (s) * 8)
    #define EMPTYB(s) (mb + (DEPTH + (s)) * 8)

    if (t == 0) {
#pragma unroll
        for (int s = 0; s < DEPTH; ++s) {
            asm volatile("mbarrier.init.shared.b64 [%0], %1;" :: "r"(FULLB(s)),  "r"(1)   : "memory");
            asm volatile("mbarrier.init.shared.b64 [%0], %1;" :: "r"(EMPTYB(s)), "r"(BLK) : "memory");
        }
    }
    __syncthreads();

    // Each CTA owns one contiguous 256-float4 pos block of image n.
    const int bx  = blockIdx.x;          // 0..255
    const int n   = bx >> 4;             // 16 pos-blocks per image
    const int pb  = bx & 15;
    const int pos = pb * BLK;            // float4 offset within plane

    const float4* xin = (const float4*)x + ((size_t)n * CIN  + cbase) * HW4 + pos;
    float4*       op  = out + ((size_t)n * OUTC + (cbase - 7)) * HW4 + pos + t;

    const unsigned sbase = (unsigned)__cvta_generic_to_shared(stg);

    // Prologue: one 4KB bulk per plane 0..7 (min nin = 25 > 8).
    if (t == 0) {
#pragma unroll
        for (int p = 0; p < DEPTH; ++p) {
            asm volatile("mbarrier.arrive.expect_tx.shared.b64 _, [%0], %1;"
                         :: "r"(FULLB(p)), "r"(STAGEB) : "memory");
            asm volatile("cp.async.bulk.shared::cta.global.mbarrier::complete_tx::bytes"
                         " [%0], [%1], %2, [%3];"
                         :: "r"(sbase + p * STAGEB), "l"(xin + (size_t)p * HW4),
                            "r"(STAGEB), "r"(FULLB(p)) : "memory");
        }
    }

    float4 acc[8];   // acc[oc & 7] accumulates output channel oc
    const unsigned myslot = sbase + t * 16;

#pragma unroll
    for (int m = 0; m < 4; ++m) {            // plane rounds; parity = m&1
#pragma unroll
        for (int u = 0; u < 8; ++u) {
            const int c = m * 8 + u;
            if (c < nin) {                   // uniform per CTA
                // Wait fill m of slot u (phase m -> parity m&1).
                {
                    uint32_t done;
                    asm volatile(
                        "{.reg .pred p;\n\t"
                        "mbarrier.try_wait.parity.acquire.cta.shared::cta.b64 p, [%1], %2;\n\t"
                        "selp.b32 %0, 1, 0, p;}"
                        : "=r"(done) : "r"(FULLB(u)), "r"((unsigned)(m & 1)) : "memory");
                    if (!done) {
                        asm volatile(
                            "{.reg .pred p;\n\t"
                            "WL%=:\n\t"
                            "mbarrier.try_wait.parity.acquire.cta.shared::cta.b64 p, [%0], %1, 0x989680;\n\t"
                            "@p bra.uni WD%=;\n\t"
                            "bra.uni WL%=;\n\t"
                            "WD%=:}"
                            :: "r"(FULLB(u)), "r"((unsigned)(m & 1)) : "memory");
                    }
                }

                float4 xv;
                asm volatile("ld.shared.v4.f32 {%0,%1,%2,%3}, [%4];"
                             : "=f"(xv.x), "=f"(xv.y), "=f"(xv.z), "=f"(xv.w)
                             : "r"(myslot + u * STAGEB));

                // Release the slot.
                asm volatile("mbarrier.arrive.shared.b64 _, [%0];"
                             :: "r"(EMPTYB(u)) : "memory");

                // t0: refill slot u with plane c+8 once all 256 arrived.
                if (t == 0 && c + DEPTH < nin) {
                    uint32_t done;
                    asm volatile(
                        "{.reg .pred p;\n\t"
                        "mbarrier.try_wait.parity.acquire.cta.shared::cta.b64 p, [%1], %2;\n\t"
                        "selp.b32 %0, 1, 0, p;}"
                        : "=r"(done) : "r"(EMPTYB(u)), "r"((unsigned)(m & 1)) : "memory");
                    if (!done) {
                        asm volatile(
                            "{.reg .pred p;\n\t"
                            "EL%=:\n\t"
                            "mbarrier.try_wait.parity.acquire.cta.shared::cta.b64 p, [%0], %1, 0x989680;\n\t"
                            "@p bra.uni ED%=;\n\t"
                            "bra.uni EL%=;\n\t"
                            "ED%=:}"
                            :: "r"(EMPTYB(u)), "r"((unsigned)(m & 1)) : "memory");
                    }
                    asm volatile("mbarrier.arrive.expect_tx.shared.b64 _, [%0], %1;"
                                 :: "r"(FULLB(u)), "r"(STAGEB) : "memory");
                    asm volatile("cp.async.bulk.shared::cta.global.mbarrier::complete_tx::bytes"
                                 " [%0], [%1], %2, [%3];"
                                 :: "r"(sbase + u * STAGEB), "l"(xin + (size_t)(c + DEPTH) * HW4),
                                    "r"(STAGEB), "r"(FULLB(u)) : "memory");
                }

                const float4 w0 = sDW[c * 2];       // k = 0..3
                const float4 w1 = sDW[c * 2 + 1];   // k = 4..7
                const float  bb = sB[c];

                // k=7 completes output c-7 (acc slot (u+1)&7), then emit.
                {
                    const int s = (u + 1) & 7;
                    acc[s].x = fmaf(w1.w, xv.x, acc[s].x);
                    acc[s].y = fmaf(w1.w, xv.y, acc[s].y);
                    acc[s].z = fmaf(w1.w, xv.z, acc[s].z);
                    acc[s].w = fmaf(w1.w, xv.w, acc[s].w);
                    if (c >= 7)                      // compile-time for m>=1
                        __stcs(op + (size_t)c * HW4, acc[s]);
                }
                {
                    const int s = (u + 2) & 7;
                    acc[s].x = fmaf(w1.z, xv.x, acc[s].x);
                    acc[s].y = fmaf(w1.z, xv.y, acc[s].y);
                    acc[s].z = fmaf(w1.z, xv.z, acc[s].z);
                    acc[s].w = fmaf(w1.z, xv.w, acc[s].w);
                }
                {
                    const int s = (u + 3) & 7;
                    acc[s].x = fmaf(w1.y, xv.x, acc[s].x);
                    acc[s].y = fmaf(w1.y, xv.y, acc[s].y);
                    acc[s].z = fmaf(w1.y, xv.z, acc[s].z);
                    acc[s].w = fmaf(w1.y, xv.w, acc[s].w);
                }
                {
                    const int s = (u + 4) & 7;
                    acc[s].x = fmaf(w1.x, xv.x, acc[s].x);
                    acc[s].y = fmaf(w1.x, xv.y, acc[s].y);
                    acc[s].z = fmaf(w1.x, xv.z, acc[s].z);
                    acc[s].w = fmaf(w1.x, xv.w, acc[s].w);
                }
                {
                    const int s = (u + 5) & 7;
                    acc[s].x = fmaf(w0.w, xv.x, acc[s].x);
                    acc[s].y = fmaf(w0.w, xv.y, acc[s].y);
                    acc[s].z = fmaf(w0.w, xv.z, acc[s].z);
                    acc[s].w = fmaf(w0.w, xv.w, acc[s].w);
                }
                {
                    const int s = (u + 6) & 7;
                    acc[s].x = fmaf(w0.z, xv.x, acc[s].x);
                    acc[s].y = fmaf(w0.z, xv.y, acc[s].y);
                    acc[s].z = fmaf(w0.z, xv.z, acc[s].z);
                    acc[s].w = fmaf(w0.z, xv.w, acc[s].w);
                }
                {
                    const int s = (u + 7) & 7;
                    acc[s].x = fmaf(w0.y, xv.x, acc[s].x);
                    acc[s].y = fmaf(w0.y, xv.y, acc[s].y);
                    acc[s].z = fmaf(w0.y, xv.z, acc[s].z);
                    acc[s].w = fmaf(w0.y, xv.w, acc[s].w);
                }
                // k=0: (re)init acc slot u for output c.
                acc[u].x = fmaf(w0.x, xv.x, bb);
                acc[u].y = fmaf(w0.x, xv.y, bb);
                acc[u].z = fmaf(w0.x, xv.z, bb);
                acc[u].w = fmaf(w0.x, xv.w, bb);
            }
        }
    }
}

extern "C" void kernel_launch(void* const* d_in, const int* in_sizes, int n_in,
                              void* d_out, int out_size) {
    const float* x  = (const float*)d_in[0];
    const float* Wg = (const float*)d_in[1];
    const float* b  = (const float*)d_in[2];
    float4* out = (float4*)d_out;

    dim3 grid(65536 / BLK, NCHUNK);
    neigh_conv_kernel<<<grid, BLK>>>(x, Wg, b, out);
}

// round 16
// speedup vs baseline: 1.0075x; 1.0075x over previous
#include <cuda_runtime.h>
#include <cstdint>

// neigh_Conv: out[n,c,h,w] = b[c] + sum_{k<8} W[c,k] * x[n,c+k,h,w]
// x: (16, 200, 128, 128) f32 -> out: (16, 193, 128, 128) f32
//
// R16 = R15 (TMA 1D bulk staging, 4KB/plane/CTA, diagonal zero-padded
// weights, 8-slot acc ring) with:
//  - stage DEPTH 8 -> 16 (TMA's UBLKCP queue has no per-warp LDGSTS
//    wavefront pathology; 3 CTAs/SM x 16 x 4KB = 192KB in flight/SM)
//  - empty mbarriers (256 ATOMS arrives/plane) replaced by ONE
//    __syncthreads() per plane; consumption is lockstep so t0 can then
//    safely recycle the slot.

#define HW4    4096   // 128*128/4 float4 per plane
#define CIN    200
#define OUTC   193
#define NCHUNK 8
#define CHG    25     // output channels per chunk (last: 18)
#define DEPTH  16     // multiple of 8 (acc-ring congruence rule)
#define LOOPN  32     // 2 * DEPTH, >= max nin (=32) exactly
#define BLK    256
#define STAGEB (BLK * 16)   // 4096 bytes per stage

__global__ __launch_bounds__(BLK)
void neigh_conv_kernel(const float* __restrict__ x,
                       const float* __restrict__ Wg,   // (193, 8) row-major
                       const float* __restrict__ b,
                       float4* __restrict__ out) {
    __shared__ float4 stg[DEPTH * BLK];                 // 64 KB stages
    __shared__ float4 sDW[32 * 2];                      // dW[c], c=0..31
    __shared__ float  sB[32];
    __shared__ __align__(8) unsigned long long mbar[DEPTH];  // full barriers

    const int t     = threadIdx.x;
    const int cbase = blockIdx.y * CHG;
    const int nout  = min(CHG, OUTC - cbase);   // 25 or 18
    const int nin   = nout + 7;                 // 32 or 25

    // Diagonal weights: dW[c][k] = W[c-k][k] or 0.  (256 entries, 1 per thread)
    float* sDWf = (float*)sDW;
    {
        const int c = t >> 3, k = t & 7;
        const int oc = c - k;
        sDWf[t] = ((unsigned)oc < (unsigned)nout) ? Wg[(cbase + oc) * 8 + k] : 0.0f;
    }
    if (t < 32) sB[t] = (t < nout) ? b[cbase + t] : 0.0f;

    const unsigned mb = (unsigned)__cvta_generic_to_shared(mbar);
    #define FULLB(s) (mb + (s) * 8)

    if (t == 0) {
#pragma unroll
        for (int s = 0; s < DEPTH; ++s)
            asm volatile("mbarrier.init.shared.b64 [%0], %1;"
                         :: "r"(FULLB(s)), "r"(1) : "memory");
    }
    __syncthreads();

    // Each CTA owns one contiguous 256-float4 pos block of image n.
    const int bx  = blockIdx.x;          // 0..255
    const int n   = bx >> 4;
    const int pos = (bx & 15) * BLK;     // float4 offset within plane

    const float4* xin = (const float4*)x + ((size_t)n * CIN  + cbase) * HW4 + pos;
    float4*       op  = out + ((size_t)n * OUTC + (cbase - 7)) * HW4 + pos + t;

    const unsigned sbase = (unsigned)__cvta_generic_to_shared(stg);

    // Prologue: one 4KB bulk per plane 0..15 (min nin = 25 > 16).
    if (t == 0) {
#pragma unroll
        for (int p = 0; p < DEPTH; ++p) {
            asm volatile("mbarrier.arrive.expect_tx.shared.b64 _, [%0], %1;"
                         :: "r"(FULLB(p)), "r"(STAGEB) : "memory");
            asm volatile("cp.async.bulk.shared::cta.global.mbarrier::complete_tx::bytes"
                         " [%0], [%1], %2, [%3];"
                         :: "r"(sbase + p * STAGEB), "l"(xin + (size_t)p * HW4),
                            "r"(STAGEB), "r"(FULLB(p)) : "memory");
        }
    }

    float4 acc[8];   // acc[oc & 7] accumulates output channel oc
    const unsigned myslot = sbase + t * 16;

#pragma unroll
    for (int m = 0; m < 2; ++m) {            // fill round; parity = m
#pragma unroll
        for (int u = 0; u < DEPTH; ++u) {
            const int c = m * DEPTH + u;     // c&7 == u&7 (16 % 8 == 0)
            if (c < nin) {                   // uniform per CTA
                // Wait fill round m of slot u.
                {
                    uint32_t done;
                    asm volatile(
                        "{.reg .pred p;\n\t"
                        "mbarrier.try_wait.parity.acquire.cta.shared::cta.b64 p, [%1], %2;\n\t"
                        "selp.b32 %0, 1, 0, p;}"
                        : "=r"(done) : "r"(FULLB(u)), "r"((unsigned)m) : "memory");
                    if (!done) {
                        asm volatile(
                            "{.reg .pred p;\n\t"
                            "WL%=:\n\t"
                            "mbarrier.try_wait.parity.acquire.cta.shared::cta.b64 p, [%0], %1, 0x989680;\n\t"
                            "@p bra.uni WD%=;\n\t"
                            "bra.uni WL%=;\n\t"
                            "WD%=:}"
                            :: "r"(FULLB(u)), "r"((unsigned)m) : "memory");
                    }
                }

                float4 xv;
                asm volatile("ld.shared.v4.f32 {%0,%1,%2,%3}, [%4];"
                             : "=f"(xv.x), "=f"(xv.y), "=f"(xv.z), "=f"(xv.w)
                             : "r"(myslot + u * STAGEB));

                // All threads have consumed plane c -> slot u recyclable.
                __syncthreads();

                // t0 recycles slot u with plane c+16.
                if (t == 0 && c + DEPTH < nin) {
                    asm volatile("mbarrier.arrive.expect_tx.shared.b64 _, [%0], %1;"
                                 :: "r"(FULLB(u)), "r"(STAGEB) : "memory");
                    asm volatile("cp.async.bulk.shared::cta.global.mbarrier::complete_tx::bytes"
                                 " [%0], [%1], %2, [%3];"
                                 :: "r"(sbase + u * STAGEB), "l"(xin + (size_t)(c + DEPTH) * HW4),
                                    "r"(STAGEB), "r"(FULLB(u)) : "memory");
                }

                const float4 w0 = sDW[c * 2];       // k = 0..3
                const float4 w1 = sDW[c * 2 + 1];   // k = 4..7
                const float  bb = sB[c];

                // k=7 completes output c-7 (acc slot (u+1)&7), then emit.
                {
                    const int s = (u + 1) & 7;
                    acc[s].x = fmaf(w1.w, xv.x, acc[s].x);
                    acc[s].y = fmaf(w1.w, xv.y, acc[s].y);
                    acc[s].z = fmaf(w1.w, xv.z, acc[s].z);
                    acc[s].w = fmaf(w1.w, xv.w, acc[s].w);
                    if (c >= 7)                      // compile-time guard
                        __stcs(op + (size_t)c * HW4, acc[s]);
                }
                {
                    const int s = (u + 2) & 7;
                    acc[s].x = fmaf(w1.z, xv.x, acc[s].x);
                    acc[s].y = fmaf(w1.z, xv.y, acc[s].y);
                    acc[s].z = fmaf(w1.z, xv.z, acc[s].z);
                    acc[s].w = fmaf(w1.z, xv.w, acc[s].w);
                }
                {
                    const int s = (u + 3) & 7;
                    acc[s].x = fmaf(w1.y, xv.x, acc[s].x);
                    acc[s].y = fmaf(w1.y, xv.y, acc[s].y);
                    acc[s].z = fmaf(w1.y, xv.z, acc[s].z);
                    acc[s].w = fmaf(w1.y, xv.w, acc[s].w);
                }
                {
                    const int s = (u + 4) & 7;
                    acc[s].x = fmaf(w1.x, xv.x, acc[s].x);
                    acc[s].y = fmaf(w1.x, xv.y, acc[s].y);
                    acc[s].z = fmaf(w1.x, xv.z, acc[s].z);
                    acc[s].w = fmaf(w1.x, xv.w, acc[s].w);
                }
                {
                    const int s = (u + 5) & 7;
                    acc[s].x = fmaf(w0.w, xv.x, acc[s].x);
                    acc[s].y = fmaf(w0.w, xv.y, acc[s].y);
                    acc[s].z = fmaf(w0.w, xv.z, acc[s].z);
                    acc[s].w = fmaf(w0.w, xv.w, acc[s].w);
                }
                {
                    const int s = (u + 6) & 7;
                    acc[s].x = fmaf(w0.z, xv.x, acc[s].x);
                    acc[s].y = fmaf(w0.z, xv.y, acc[s].y);
                    acc[s].z = fmaf(w0.z, xv.z, acc[s].z);
                    acc[s].w = fmaf(w0.z, xv.w, acc[s].w);
                }
                {
                    const int s = (u + 7) & 7;
                    acc[s].x = fmaf(w0.y, xv.x, acc[s].x);
                    acc[s].y = fmaf(w0.y, xv.y, acc[s].y);
                    acc[s].z = fmaf(w0.y, xv.z, acc[s].z);
                    acc[s].w = fmaf(w0.y, xv.w, acc[s].w);
                }
                // k=0: (re)init acc slot (u&7) for output c.
                {
                    const int s = u & 7;
                    acc[s].x = fmaf(w0.x, xv.x, bb);
                    acc[s].y = fmaf(w0.x, xv.y, bb);
                    acc[s].z = fmaf(w0.x, xv.z, bb);
                    acc[s].w = fmaf(w0.x, xv.w, bb);
                }
            }
        }
    }
}

extern "C" void kernel_launch(void* const* d_in, const int* in_sizes, int n_in,
                              void* d_out, int out_size) {
    const float* x  = (const float*)d_in[0];
    const float* Wg = (const float*)d_in[1];
    const float* b  = (const float*)d_in[2];
    float4* out = (float4*)d_out;

    dim3 grid(65536 / BLK, NCHUNK);
    neigh_conv_kernel<<<grid, BLK>>>(x, Wg, b, out);
}

// round 17
// speedup vs baseline: 1.0089x; 1.0014x over previous
#include <cuda_runtime.h>

// neigh_Conv: out[n,c,h,w] = b[c] + sum_{k<8} W[c,k] * x[n,c+k,h,w]
// x: (16, 200, 128, 128) f32 -> out: (16, 193, 128, 128) f32
//
// R17 = R11 engine (cp.async DEPTH=8 consume-then-refill, diagonal
// zero-padded weights, 8-slot acc ring, 256-thr CTAs, 8 channel-chunks)
// with GRADED chunk sizes [32,32,32,28,24,20,15,10] (sum 193): CTAs
// dispatch in bid order, so the last-launched CTAs (by=6,7) carry ~3x
// less work -> drain tail ~halved. Steady state identical to R11
// (same chunk count => same halo, same prologue fraction).

#define HW4    4096   // 128*128/4 float4 per plane
#define CIN    200
#define OUTC   193
#define NCHUNK 8
#define NMAX   40     // max nloop = round8(32+7)
#define DEPTH  8
#define BLK    256

__constant__ int CBASE[NCHUNK + 1] = {0, 32, 64, 96, 124, 148, 168, 183, 193};

__global__ __launch_bounds__(BLK)
void neigh_conv_kernel(const float* __restrict__ x,
                       const float* __restrict__ Wg,   // (193, 8) row-major
                       const float* __restrict__ b,
                       float4* __restrict__ out) {
    __shared__ float4 stg[DEPTH * BLK];    // [slot][tid], 32 KB
    __shared__ float4 sDW[NMAX * 2];       // dW[c] = 8 floats (2 float4)
    __shared__ float  sB[NMAX];

    const int t     = threadIdx.x;
    const int by    = blockIdx.y;
    const int cbase = CBASE[by];
    const int nout  = CBASE[by + 1] - cbase;    // 32..10
    const int nin   = nout + 7;                 // 39..17
    const int nloop = (nin + 7) & ~7;           // round up to multiple of 8

    // dW[c][k] = W[c-k][k] if 0 <= c-k < nout else 0  (c = 0..NMAX-1)
    float* sDWf = (float*)sDW;
    for (int i = t; i < NMAX * 8; i += BLK) {
        const int c = i >> 3, k = i & 7;
        const int oc = c - k;
        sDWf[i] = ((unsigned)oc < (unsigned)nout) ? Wg[(cbase + oc) * 8 + k] : 0.0f;
    }
    if (t < NMAX) sB[t] = (t < nout) ? b[cbase + t] : 0.0f;
    __syncthreads();

    const int gid = blockIdx.x * BLK + t;    // 0..65535
    const int n   = gid >> 12;
    const int pos = gid & 4095;

    const float4* xin = (const float4*)x + ((size_t)n * CIN  + cbase) * HW4 + pos;
    // Pre-offset by -7 planes so the emit address is op + c*HW4.
    float4*       op  = out + ((size_t)n * OUTC + (cbase - 7)) * HW4 + pos;

    const unsigned sbase = (unsigned)__cvta_generic_to_shared(&stg[t]);
    // stage slot s lives at sbase + s*(BLK*16) bytes

    // Prologue: planes 0..7 fill all 8 slots (min nin = 17 > 8, all valid).
#pragma unroll
    for (int p = 0; p < DEPTH; ++p) {
        const unsigned sa = sbase + p * (BLK * 16);
        const float4* ga = xin + (size_t)p * HW4;
        asm volatile("cp.async.cg.shared.global [%0], [%1], 16;\n"
                     :: "r"(sa), "l"(ga));
        asm volatile("cp.async.commit_group;\n" ::: "memory");
    }

    float4 acc[8];   // acc[oc & 7] accumulates output channel oc

    for (int cb = 0; cb < nloop; cb += 8) {   // cb % 8 == 0 always
#pragma unroll
        for (int u = 0; u < 8; ++u) {
            const int c = cb + u;

            // Plane c is the oldest pending group (7 newer allowed).
            asm volatile("cp.async.wait_group 7;\n" ::: "memory");

            float4 xv;
            const unsigned sa = sbase + u * (BLK * 16);
            asm volatile("ld.shared.v4.f32 {%0,%1,%2,%3}, [%4];"
                         : "=f"(xv.x), "=f"(xv.y), "=f"(xv.z), "=f"(xv.w)
                         : "r"(sa));

            // Refill THIS slot with plane c+8 (fill lands >=234cyc after
            // the 29cyc LDS above -- no hazard).
            if (c + DEPTH < nin) {
                const float4* ga = xin + (size_t)(c + DEPTH) * HW4;
                asm volatile("cp.async.cg.shared.global [%0], [%1], 16;\n"
                             :: "r"(sa), "l"(ga));
            }
            asm volatile("cp.async.commit_group;\n" ::: "memory");

            const float4 w0 = sDW[c * 2];       // k = 0..3
            const float4 w1 = sDW[c * 2 + 1];   // k = 4..7
            const float  bb = sB[c];

            // k=7 completes output c-7 (acc slot (u+1)&7), then emit.
            {
                const int s = (u + 1) & 7;
                acc[s].x = fmaf(w1.w, xv.x, acc[s].x);
                acc[s].y = fmaf(w1.w, xv.y, acc[s].y);
                acc[s].z = fmaf(w1.w, xv.z, acc[s].z);
                acc[s].w = fmaf(w1.w, xv.w, acc[s].w);
                if ((unsigned)(c - 7) < (unsigned)nout)
                    __stcs(op + (size_t)c * HW4, acc[s]);
            }
            // k = 6..1 (weights zero outside valid range -> no guards).
            {
                const int s = (u + 2) & 7;
                acc[s].x = fmaf(w1.z, xv.x, acc[s].x);
                acc[s].y = fmaf(w1.z, xv.y, acc[s].y);
                acc[s].z = fmaf(w1.z, xv.z, acc[s].z);
                acc[s].w = fmaf(w1.z, xv.w, acc[s].w);
            }
            {
                const int s = (u + 3) & 7;
                acc[s].x = fmaf(w1.y, xv.x, acc[s].x);
                acc[s].y = fmaf(w1.y, xv.y, acc[s].y);
                acc[s].z = fmaf(w1.y, xv.z, acc[s].z);
                acc[s].w = fmaf(w1.y, xv.w, acc[s].w);
            }
            {
                const int s = (u + 4) & 7;
                acc[s].x = fmaf(w1.x, xv.x, acc[s].x);
                acc[s].y = fmaf(w1.x, xv.y, acc[s].y);
                acc[s].z = fmaf(w1.x, xv.z, acc[s].z);
                acc[s].w = fmaf(w1.x, xv.w, acc[s].w);
            }
            {
                const int s = (u + 5) & 7;
                acc[s].x = fmaf(w0.w, xv.x, acc[s].x);
                acc[s].y = fmaf(w0.w, xv.y, acc[s].y);
                acc[s].z = fmaf(w0.w, xv.z, acc[s].z);
                acc[s].w = fmaf(w0.w, xv.w, acc[s].w);
            }
            {
                const int s = (u + 6) & 7;
                acc[s].x = fmaf(w0.z, xv.x, acc[s].x);
                acc[s].y = fmaf(w0.z, xv.y, acc[s].y);
                acc[s].z = fmaf(w0.z, xv.z, acc[s].z);
                acc[s].w = fmaf(w0.z, xv.w, acc[s].w);
            }
            {
                const int s = (u + 7) & 7;
                acc[s].x = fmaf(w0.y, xv.x, acc[s].x);
                acc[s].y = fmaf(w0.y, xv.y, acc[s].y);
                acc[s].z = fmaf(w0.y, xv.z, acc[s].z);
                acc[s].w = fmaf(w0.y, xv.w, acc[s].w);
            }
            // k=0: (re)init acc slot u for output c with bias + 1st term.
            acc[u].x = fmaf(w0.x, xv.x, bb);
            acc[u].y = fmaf(w0.x, xv.y, bb);
            acc[u].z = fmaf(w0.x, xv.z, bb);
            acc[u].w = fmaf(w0.x, xv.w, bb);
        }
    }
}

extern "C" void kernel_launch(void* const* d_in, const int* in_sizes, int n_in,
                              void* d_out, int out_size) {
    const float* x  = (const float*)d_in[0];
    const float* Wg = (const float*)d_in[1];
    const float* b  = (const float*)d_in[2];
    float4* out = (float4*)d_out;

    dim3 grid(65536 / BLK, NCHUNK);
    neigh_conv_kernel<<<grid, BLK>>>(x, Wg, b, out);
}